// round 15
// baseline (speedup 1.0000x reference)
#include <cuda_runtime.h>
#include <math.h>

#define BB 8
#define CC 4
#define HH 192
#define WW 192
#define HW (HH*WW)
#define NP 24          // (batch, class) pairs
#define NM 48          // (pair, direction): even = pred surface, odd = gt surface
#define SENT_KEY 73727 // key for empty source surface (f = 1e9)
#define WPR 6          // u32 words per 192-bit row
#define WPM 1152       // words per mask bitmap
#define COLS2 96       // columns per K2 block
#define NSEG 8
#define SEGR 24
#define CHR 48         // rows per K3 chunk
#define NCHK 4

__device__ __align__(16) unsigned char  d_pred[BB*HW];
__device__ unsigned       d_surf[NM*WPM];     // surface bitmaps
__device__ unsigned short d_g16[NM*HW];       // column EDT squared (65535 = inf)
__device__ int            d_keys[NM*HW];      // keys at fixed voxel positions
__device__ int            d_hist[NM*288];
__device__ int            d_max[NM];
__device__ int            d_tick[NM];
__device__ int            d_done;
__device__ float          d_res[NM*2];        // [m][0]=p95, [m][1]=p100

// ---------------------------------------------------------------- K1: argmax (softmax monotone; first-max ties) + clears
__global__ void argmax_kernel(const float* __restrict__ logits) {
    int idx = blockIdx.x*blockDim.x + threadIdx.x;
    if (idx < NM) { d_tick[idx] = 0; d_max[idx] = 0; }
    if (idx == NM) d_done = 0;
    if (idx < NM*288) d_hist[idx] = 0;
    int pix4 = idx * 4;
    if (pix4 >= BB*HW) return;
    int b = pix4 / HW;
    int p = pix4 - b*HW;
    const float* base = logits + (size_t)b*CC*HW + p;
    float4 v0 = *(const float4*)(base);
    float4 v1 = *(const float4*)(base + HW);
    float4 v2 = *(const float4*)(base + 2*HW);
    float4 v3 = *(const float4*)(base + 3*HW);
    uchar4 r;
    #define AMAX(cp, dst) { \
        float bv = v0.cp; int bi = 0; \
        if (v1.cp > bv) { bv = v1.cp; bi = 1; } \
        if (v2.cp > bv) { bv = v2.cp; bi = 2; } \
        if (v3.cp > bv) { bv = v3.cp; bi = 3; } \
        dst = (unsigned char)bi; }
    AMAX(x, r.x) AMAX(y, r.y) AMAX(z, r.z) AMAX(w, r.w)
    #undef AMAX
    *(uchar4*)(d_pred + pix4) = r;
}

// ---------------------------------------------------------------- K2: surfaces + segmented column EDT (mask x col-half)
// target is int32 (JAX x64-disabled downcasts the reference's int64). Border = background.
__global__ void __launch_bounds__(1024) prep_kernel(const int* __restrict__ target) {
    __shared__ unsigned fgP[WPM], fgG[WPM], sfP[WPM], sfG[WPM];
    __shared__ unsigned short pk[HH*COLS2];            // packed (dn | up<<8)
    __shared__ unsigned char outd[NSEG*COLS2], outu[NSEG*COLS2];
    __shared__ unsigned char incd[NSEG*COLS2], incu[NSEG*COLS2];
    const int T = 1024;
    int m = blockIdx.x;
    int y = blockIdx.y;                                // column half
    int j0 = y*COLS2;
    int pairI = m >> 1;
    int b = pairI / 3;
    int c = pairI - b*3 + 1;
    int tid = threadIdx.x;

    // A: fg bitmaps (full image, both masks)
    {
        unsigned crep = (unsigned)c * 0x01010101u;
        const uint4* pb = (const uint4*)(d_pred + b*HW);
        const int4*  tb = (const int4*)(target + (size_t)b*HW);
        for (int k = tid; k < WPM; k += T) {
            unsigned wp = 0;
            uint4 pa = pb[k*2], pc = pb[k*2 + 1];
            #define NIB(word, sh) { \
                unsigned nb = ((__vcmpeq4(word, crep) & 0x01010101u) * 0x01020408u) >> 24; \
                wp |= nb << (sh); }
            NIB(pa.x, 0) NIB(pa.y, 4) NIB(pa.z, 8) NIB(pa.w, 12)
            NIB(pc.x, 16) NIB(pc.y, 20) NIB(pc.z, 24) NIB(pc.w, 28)
            #undef NIB
            fgP[k] = wp;
            unsigned wg = 0;
            #pragma unroll
            for (int q = 0; q < 8; q++) {
                int4 tv = tb[k*8 + q];
                wg |= ((tv.x==c)?1u:0u) << (4*q);
                wg |= ((tv.y==c)?2u:0u) << (4*q);
                wg |= ((tv.z==c)?4u:0u) << (4*q);
                wg |= ((tv.w==c)?8u:0u) << (4*q);
            }
            fgG[k] = wg;
        }
    }
    __syncthreads();

    // B: 4-neighbor surfaces via bit ops
    for (int idx = tid; idx < 2*WPM; idx += T) {
        const unsigned* fg = (idx < WPM) ? fgP : fgG;
        unsigned* sf = (idx < WPM) ? sfP : sfG;
        int k = (idx < WPM) ? idx : idx - WPM;
        int i = k / 6, w = k - (k/6)*6;
        unsigned f  = fg[k];
        unsigned up = (i > 0)    ? fg[k-6] : 0u;
        unsigned dn = (i < HH-1) ? fg[k+6] : 0u;
        unsigned lw = (w > 0) ? fg[k-1] : 0u;
        unsigned nx = (w < 5) ? fg[k+1] : 0u;
        unsigned lf = (f << 1) | (lw >> 31);
        unsigned rt = (f >> 1) | (nx << 31);
        sf[k] = f & ~(up & dn & lf & rt);
    }
    __syncthreads();

    const unsigned* sS = (m & 1) ? sfG : sfP;          // this mask's own surface
    if (y == 0)
        for (int k = tid; k < WPM; k += T) d_surf[m*WPM + k] = sS[k];

    // C1: segmented local scans (96 cols x 8 segs of 24 rows)
    if (tid < NSEG*COLS2) {
        int jl = tid % COLS2, s = tid / COLS2;
        int j = j0 + jl;
        int r0 = s*SEGR;
        int ws = j >> 5; unsigned bm = 1u << (j & 31);
        int cnt = 255;
        #pragma unroll
        for (int k = 0; k < SEGR; k++) {
            bool sv = (sS[(r0 + k)*6 + ws] & bm) != 0;
            cnt = sv ? 0 : min(cnt + 1, 255);
            pk[(r0 + k)*COLS2 + jl] = (unsigned short)cnt;
        }
        outd[s*COLS2 + jl] = (unsigned char)cnt;
        cnt = 255;
        #pragma unroll
        for (int k = SEGR - 1; k >= 0; k--) {
            bool sv = (sS[(r0 + k)*6 + ws] & bm) != 0;
            cnt = sv ? 0 : min(cnt + 1, 255);
            pk[(r0 + k)*COLS2 + jl] |= (unsigned short)(cnt << 8);
        }
        outu[s*COLS2 + jl] = (unsigned char)cnt;
    }
    __syncthreads();

    // C2: per-column incoming distances across segments
    if (tid < COLS2) {
        int jl = tid;
        int a = 255;
        incd[0*COLS2 + jl] = 255;
        #pragma unroll
        for (int s = 1; s < NSEG; s++) {
            a = min(255, min((int)outd[(s-1)*COLS2 + jl], a + SEGR));
            incd[s*COLS2 + jl] = (unsigned char)a;
        }
        a = 255;
        incu[(NSEG-1)*COLS2 + jl] = 255;
        #pragma unroll
        for (int s = NSEG - 2; s >= 0; s--) {
            a = min(255, min((int)outu[(s+1)*COLS2 + jl], a + SEGR));
            incu[s*COLS2 + jl] = (unsigned char)a;
        }
    }
    __syncthreads();

    // C3: merge -> global g (u16 squared distance; 65535 = inf)
    for (int pos = tid; pos < HH*COLS2; pos += T) {
        int i = pos / COLS2, jl = pos - (pos/COLS2)*COLS2;
        int s = i / SEGR, il = i - s*SEGR;
        unsigned short pv = pk[pos];
        int dglob = min((int)(pv & 255), min(255, (int)incd[s*COLS2 + jl] + il + 1));
        int uglob = min((int)(pv >> 8),  min(255, (int)incu[s*COLS2 + jl] + (SEGR - il)));
        int d = min(dglob, uglob);
        d_g16[m*HW + i*WW + j0 + jl] = (d >= HH) ? (unsigned short)65535 : (unsigned short)(d*d);
    }
}

// ---------------------------------------------------------------- K3: pruned min-plus at samples + fused selection (mask x row-chunk)
__global__ void __launch_bounds__(256) dist_kernel(float* __restrict__ out) {
    __shared__ unsigned short gRow[CHR*WW];            // 18 KB
    __shared__ unsigned oppW[WPM];                     // full opp bitmap (only CHR*WPR used in phase E)
    __shared__ int hist[288];
    __shared__ int fine[256];
    __shared__ int misc[6];
    const int T = 256;
    int m = blockIdx.x;
    int r0 = blockIdx.y * CHR;
    int tid = threadIdx.x;
    int lane = tid & 31;

    for (int k = tid; k < CHR*WW/2; k += T)
        ((unsigned*)gRow)[k] = ((const unsigned*)(d_g16 + m*HW + r0*WW))[k];
    for (int k = tid; k < CHR*WPR; k += T)
        oppW[k] = d_surf[(m^1)*WPM + r0*WPR + k];
    for (int k = tid; k < 288; k += T) hist[k] = 0;
    __syncthreads();

    int locmax = 0;
    int* gkeys = d_keys + m*HW;
    for (int pos = tid; pos < CHR*WW; pos += T) {
        int lr = pos / WW, j = pos - lr*WW;
        bool smp = (oppW[lr*WPR + (j >> 5)] >> (j & 31)) & 1;
        int key = 0;
        if (smp) {
            const unsigned short* grow = gRow + lr*WW;
            unsigned short raw = grow[j];
            float v = (raw == 65535) ? 1e9f : (float)raw;
            for (int dd = 1; dd < WW; dd += 2) {
                float d2a = (float)(dd*dd);
                if (d2a >= v) break;                   // exact: g >= 0
                float d2b = (float)((dd+1)*(dd+1));
                int jl = j - dd, jr = j + dd;
                float ca = 3e9f, cb = 3e9f, cc = 3e9f, cd = 3e9f;
                unsigned short u;
                if (jl >= 0)     { u = grow[jl];   ca = d2a + ((u==65535)?1e9f:(float)u); }
                if (jr < WW)     { u = grow[jr];   cb = d2a + ((u==65535)?1e9f:(float)u); }
                if (jl - 1 >= 0) { u = grow[jl-1]; cc = d2b + ((u==65535)?1e9f:(float)u); }
                if (jr + 1 < WW) { u = grow[jr+1]; cd = d2b + ((u==65535)?1e9f:(float)u); }
                v = fminf(fminf(v, fminf(ca, cb)), fminf(cc, cd));
            }
            key = (v > 73000.0f) ? SENT_KEY : (int)v;  // exact integer or ~1e9
            gkeys[(r0 + lr)*WW + j] = key;
            locmax = max(locmax, key);
        }
        unsigned am = __ballot_sync(0xffffffffu, smp);
        if (smp) {
            int bin = key >> 8;
            unsigned grp = __match_any_sync(am, bin);
            if ((int)(__ffs(grp) - 1) == lane) atomicAdd(&hist[bin], __popc(grp));
        }
    }
    #pragma unroll
    for (int off = 16; off > 0; off >>= 1) locmax = max(locmax, __shfl_down_sync(0xffffffffu, locmax, off));
    if (lane == 0 && locmax > 0) atomicMax(&d_max[m], locmax);
    __syncthreads();
    for (int k = tid; k < 288; k += T)
        if (hist[k]) atomicAdd(&d_hist[m*288 + k], hist[k]);

    // ticket: last chunk of this mask runs selection
    __threadfence();
    __syncthreads();
    if (tid == 0) {
        misc[0] = (atomicAdd(&d_tick[m], 1) == NCHK - 1) ? 1 : 0;
        if (misc[0]) d_tick[m] = 0;                    // reset for next replay
    }
    __syncthreads();
    if (!misc[0]) return;
    __threadfence();

    // selection: n = |opposite surface|; p100 = max; p95 = rank ceil(0.95f*n)
    for (int k = tid; k < WPM; k += T) oppW[k] = d_surf[(m^1)*WPM + k];
    if (tid == 0) misc[1] = 0;
    __syncthreads();
    {
        int pc = 0;
        for (int k = tid; k < WPM; k += T) pc += __popc(oppW[k]);
        #pragma unroll
        for (int off = 16; off > 0; off >>= 1) pc += __shfl_down_sync(0xffffffffu, pc, off);
        if (lane == 0) atomicAdd(&misc[1], pc);
    }
    __syncthreads();
    int n = misc[1];
    if (n == 0) {
        if (tid == 0) { d_res[m*2] = INFINITY; d_res[m*2+1] = INFINITY; }
    } else {
        for (int k = tid; k < 288; k += T) hist[k] = d_hist[m*288 + k];
        if (tid < 256) fine[tid] = 0;
        __syncthreads();
        if (tid == 0) {
            int r95 = (int)ceilf(0.95f * (float)n);    // matches jnp f32 semantics
            r95 = max(1, min(r95, n));
            int cum = 0, cb = 287;
            for (int k = 0; k < 288; k++) {
                if (cum + hist[k] >= r95) { cb = k; break; }
                cum += hist[k];
            }
            misc[2] = cb; misc[3] = r95 - cum;
        }
        __syncthreads();
        int cb = misc[2];
        for (int pos = tid; pos < HW; pos += T) {
            bool smp = (oppW[pos >> 5] >> (pos & 31)) & 1;   // 192 cols -> linear bit index == pixel
            bool hit = false; int key = 0;
            if (smp) { key = gkeys[pos]; hit = ((key >> 8) == cb); }
            unsigned am = __ballot_sync(0xffffffffu, hit);
            if (hit) {
                int fb = key & 255;
                unsigned grp = __match_any_sync(am, fb);
                if ((int)(__ffs(grp) - 1) == lane) atomicAdd(&fine[fb], __popc(grp));
            }
        }
        __syncthreads();
        if (tid == 0) {
            int cum = 0, key95 = cb << 8;
            for (int k = 0; k < 256; k++) {
                cum += fine[k];
                if (cum >= misc[3]) { key95 += k; break; }
            }
            int keymax = d_max[m];
            d_res[m*2+0] = (key95  == SENT_KEY) ? sqrtf(1e9f) : sqrtf((float)key95);
            d_res[m*2+1] = (keymax == SENT_KEY) ? sqrtf(1e9f) : sqrtf((float)keymax);
        }
    }

    // final reduce: last mask to finish (order-independent -> deterministic)
    __threadfence();
    __syncthreads();
    if (tid == 0 && atomicAdd(&d_done, 1) == NM - 1) {
        __threadfence();
        float s100 = 0.0f, s95 = 0.0f;
        #pragma unroll
        for (int p = 0; p < NP; p++) {
            s95  += fmaxf(d_res[(2*p)*2 + 0], d_res[(2*p+1)*2 + 0]);
            s100 += fmaxf(d_res[(2*p)*2 + 1], d_res[(2*p+1)*2 + 1]);
        }
        out[0] = s100 / (float)NP;
        out[1] = s95  / (float)NP;
        d_done = 0;                                    // reset for next replay
    }
}

extern "C" void kernel_launch(void* const* d_in, const int* in_sizes, int n_in,
                              void* d_out, int out_size) {
    const float* logits = (const float*)d_in[0];
    const int*   target = (const int*)d_in[1];
    float* out = (float*)d_out;

    argmax_kernel<<<(BB*HW/4 + 255)/256, 256>>>(logits);
    prep_kernel  <<<dim3(NM, 2), 1024>>>(target);
    dist_kernel  <<<dim3(NM, NCHK), 256>>>(out);
}

// round 16
// speedup vs baseline: 2.4726x; 2.4726x over previous
#include <cuda_runtime.h>
#include <math.h>

#define BB 8
#define CC 4
#define HH 192
#define WW 192
#define HW (HH*WW)
#define NP 24          // (batch, class) pairs
#define NM 48          // (pair, direction)
#define SENT_KEY 73727 // key for empty source surface (f = 1e9)
#define WPM 1152       // u32 words per mask bitmap (6 per row)
#define NSEG 8
#define SEGR 24
#define GEMPTY (1 << 27)

// dynamic smem layout (bytes)
#define OFF_G     0        // int [HW] 147456 (C1 scratch: dn u16 | up u16; final: d^2 or GEMPTY)
#define OFF_FGP   147456   // u32 [1152]
#define OFF_FGG   152064   // u32 [1152]
#define OFF_SFP   156672   // u32 [1152]
#define OFF_SFG   161280   // u32 [1152]
#define OFF_OUTD  165888   // u8 [NSEG*192]
#define OFF_OUTU  167424   // u8 [NSEG*192]
#define OFF_INCD  168960   // u8 [NSEG*192]
#define OFF_INCU  170496   // u8 [NSEG*192]
#define OFF_HIST  172032   // int [288]
#define OFF_FINE  173184   // int [256]
#define OFF_MISC  174208   // int [8]
#define SMEM_TOTAL 174240

__device__ __align__(16) unsigned char d_pred[BB*HW];
__device__ int   d_keys[NM*HW];   // keys at fixed voxel positions
__device__ float d_res[NM*2];     // [m][0]=p95, [m][1]=p100
__device__ int   d_done;

extern __shared__ char smem[];

// ---------------------------------------------------------------- K1: argmax (softmax monotone; first-max ties)
__global__ void argmax_kernel(const float* __restrict__ logits) {
    int idx = blockIdx.x*blockDim.x + threadIdx.x;
    if (idx == 0) d_done = 0;
    if (idx >= BB*HW) return;
    int b = idx / HW;
    int p = idx - b*HW;
    const float* base = logits + (size_t)b*CC*HW + p;
    float v0 = base[0];
    float v1 = base[HW];
    float v2 = base[2*HW];
    float v3 = base[3*HW];
    float bv = v0; int bi = 0;
    if (v1 > bv) { bv = v1; bi = 1; }
    if (v2 > bv) { bv = v2; bi = 2; }
    if (v3 > bv) { bv = v3; bi = 3; }
    d_pred[idx] = (unsigned char)bi;
}

// ---------------------------------------------------------------- K2: one mask per block, fully fused
__global__ void __launch_bounds__(1024) mega_kernel(const int* __restrict__ target,
                                                    float* __restrict__ out) {
    int*      gS  = (int*)(smem + OFF_G);
    unsigned* fgP = (unsigned*)(smem + OFF_FGP);
    unsigned* fgG = (unsigned*)(smem + OFF_FGG);
    unsigned* sfP = (unsigned*)(smem + OFF_SFP);
    unsigned* sfG = (unsigned*)(smem + OFF_SFG);
    unsigned char* outd = (unsigned char*)(smem + OFF_OUTD);
    unsigned char* outu = (unsigned char*)(smem + OFF_OUTU);
    unsigned char* incd = (unsigned char*)(smem + OFF_INCD);
    unsigned char* incu = (unsigned char*)(smem + OFF_INCU);
    int* hist = (int*)(smem + OFF_HIST);
    int* fine = (int*)(smem + OFF_FINE);
    int* misc = (int*)(smem + OFF_MISC);

    const int T = 1024;
    int m = blockIdx.x;
    int pairI = m >> 1;
    int b = pairI / 3;
    int c = pairI - b*3 + 1;
    int tid = threadIdx.x;
    int lane = tid & 31;

    // ---- A: fg bitmaps from pred bytes / int32 target (word-per-thread, no atomics)
    // target is int32 (JAX x64-disabled downcasts the reference's int64)
    {
        unsigned crep = (unsigned)c * 0x01010101u;
        const uint4* pb = (const uint4*)(d_pred + b*HW);
        const int4*  tb = (const int4*)(target + (size_t)b*HW);
        for (int k = tid; k < WPM; k += T) {
            unsigned wp = 0;
            uint4 pa = pb[k*2], pc = pb[k*2 + 1];
            #define NIB(word, sh) { \
                unsigned nb = ((__vcmpeq4(word, crep) & 0x01010101u) * 0x01020408u) >> 24; \
                wp |= nb << (sh); }
            NIB(pa.x, 0) NIB(pa.y, 4) NIB(pa.z, 8) NIB(pa.w, 12)
            NIB(pc.x, 16) NIB(pc.y, 20) NIB(pc.z, 24) NIB(pc.w, 28)
            #undef NIB
            fgP[k] = wp;
            unsigned wg = 0;
            #pragma unroll
            for (int q = 0; q < 8; q++) {
                int4 tv = tb[k*8 + q];
                wg |= ((tv.x==c)?1u:0u) << (4*q);
                wg |= ((tv.y==c)?2u:0u) << (4*q);
                wg |= ((tv.z==c)?4u:0u) << (4*q);
                wg |= ((tv.w==c)?8u:0u) << (4*q);
            }
            fgG[k] = wg;
        }
    }
    if (tid == 0) { misc[1] = 0; misc[5] = 0; }
    for (int k = tid; k < 288; k += T) hist[k] = 0;
    if (tid < 256) fine[tid] = 0;
    __syncthreads();

    // ---- B: 4-neighbor surfaces via bit ops (image border = background)
    for (int idx = tid; idx < 2*WPM; idx += T) {
        const unsigned* fg = (idx < WPM) ? fgP : fgG;
        unsigned* sf = (idx < WPM) ? sfP : sfG;
        int k = (idx < WPM) ? idx : idx - WPM;
        int i = k / 6, w = k - (k/6)*6;
        unsigned f  = fg[k];
        unsigned up = (i > 0)    ? fg[k-6] : 0u;
        unsigned dn = (i < HH-1) ? fg[k+6] : 0u;
        unsigned lw = (w > 0) ? fg[k-1] : 0u;
        unsigned nx = (w < 5) ? fg[k+1] : 0u;
        unsigned lf = (f << 1) | (lw >> 31);
        unsigned rt = (f >> 1) | (nx << 31);
        sf[k] = f & ~(up & dn & lf & rt);
    }
    __syncthreads();

    const unsigned* sS = (m & 1) ? sfG : sfP;   // source surface (distance field of mask m)
    const unsigned* sO = (m & 1) ? sfP : sfG;   // opposite surface (sample points)

    // ---- C1: independent down/up segment scans (3072 tasks, 24-deep each)
    // down writes low u16, up writes high u16 of the same g word (byte-granular, no race)
    for (int t = tid; t < 2*NSEG*WW; t += T) {
        int down = (t < NSEG*WW);
        int tt = down ? t : t - NSEG*WW;
        int s = tt / WW, j = tt - s*WW;
        int r0 = s*SEGR;
        int ws = j >> 5; unsigned bm = 1u << (j & 31);
        unsigned short* gh = (unsigned short*)gS;
        int cnt = 255;
        if (down) {
            #pragma unroll
            for (int k = 0; k < SEGR; k++) {
                bool sv = (sS[(r0 + k)*6 + ws] & bm) != 0;
                cnt = sv ? 0 : min(cnt + 1, 255);
                gh[((r0 + k)*WW + j)*2] = (unsigned short)cnt;
            }
            outd[s*WW + j] = (unsigned char)cnt;
        } else {
            #pragma unroll
            for (int k = SEGR - 1; k >= 0; k--) {
                bool sv = (sS[(r0 + k)*6 + ws] & bm) != 0;
                cnt = sv ? 0 : min(cnt + 1, 255);
                gh[((r0 + k)*WW + j)*2 + 1] = (unsigned short)cnt;
            }
            outu[s*WW + j] = (unsigned char)cnt;
        }
    }
    __syncthreads();

    // ---- C2 (threads 0-191): per-column incoming distances across segments
    if (tid < WW) {
        int j = tid;
        int a = 255;
        incd[0*WW + j] = 255;
        #pragma unroll
        for (int s = 1; s < NSEG; s++) {
            a = min(255, min((int)outd[(s-1)*WW + j], a + SEGR));
            incd[s*WW + j] = (unsigned char)a;
        }
        a = 255;
        incu[(NSEG-1)*WW + j] = 255;
        #pragma unroll
        for (int s = NSEG - 2; s >= 0; s--) {
            a = min(255, min((int)outu[(s+1)*WW + j], a + SEGR));
            incu[s*WW + j] = (unsigned char)a;
        }
    }
    // n = |opposite surface| (concurrent popc reduce)
    {
        int pc = 0;
        for (int k = tid; k < WPM; k += T) pc += __popc(sO[k]);
        #pragma unroll
        for (int off = 16; off > 0; off >>= 1) pc += __shfl_down_sync(0xffffffffu, pc, off);
        if (lane == 0 && pc) atomicAdd(&misc[5], pc);
    }
    __syncthreads();

    // ---- C3: combine -> g int d^2 (GEMPTY = no surface in column)
    for (int pos = tid; pos < HW; pos += T) {
        int i = pos / WW, j = pos - (pos/WW)*WW;
        int s = i / SEGR, il = i - s*SEGR;
        unsigned pv = (unsigned)gS[pos];
        int dglob = min((int)(pv & 0xFFFF), min(255, (int)incd[s*WW + j] + il + 1));
        int uglob = min((int)(pv >> 16),   min(255, (int)incu[s*WW + j] + (SEGR - il)));
        int d = min(dglob, uglob);
        gS[pos] = (d >= HH) ? GEMPTY : d*d;
    }
    __syncthreads();
    int n = misc[5];

    if (n == 0) {
        if (tid == 0) { d_res[m*2] = INFINITY; d_res[m*2+1] = INFINITY; }
    } else {
        // ---- E: pure-int pruned min-plus per sample, word-per-thread bitmap iteration
        // f = min_jp (j-jp)^2 + g[jp]; outward scan stops when dd^2 >= v (g >= 0 -> exact).
        // Real candidates are ints <= 72962 < GEMPTY, so int min == reference f32 min.
        int* gkeys = d_keys + m*HW;
        int lmax = 0;
        for (int w = tid; w < WPM; w += T) {
            unsigned bits = sO[w];
            int r = w / 6, jbase = (w - r*6) * 32;
            const int* grow = gS + r*WW;
            while (bits) {
                int bpos = __ffs(bits) - 1;
                bits &= bits - 1;
                int j = jbase + bpos;
                int v = grow[j];
                for (int dd = 1; dd < WW; dd++) {
                    if (dd*dd >= v) break;
                    int d2 = dd*dd;
                    int jl = j - dd, jr = j + dd;
                    if (jl >= 0) v = min(v, d2 + grow[jl]);
                    if (jr < WW) v = min(v, d2 + grow[jr]);
                }
                int key = (v > 73000) ? SENT_KEY : v;
                gkeys[r*WW + j] = key;
                lmax = max(lmax, key);
                atomicAdd(&hist[key >> 8], 1);
            }
        }
        #pragma unroll
        for (int off = 16; off > 0; off >>= 1) lmax = max(lmax, __shfl_down_sync(0xffffffffu, lmax, off));
        if (lane == 0 && lmax > 0) atomicMax(&misc[1], lmax);
        __syncthreads();

        // ---- F: p95 = rank ceil(0.95f*n) via coarse+fine; p100 = max
        if (tid == 0) {
            int r95 = (int)ceilf(0.95f * (float)n);      // matches jnp f32 semantics
            r95 = max(1, min(r95, n));
            int cum = 0, cb = 287;
            for (int k = 0; k < 288; k++) {
                if (cum + hist[k] >= r95) { cb = k; break; }
                cum += hist[k];
            }
            misc[2] = cb; misc[3] = r95 - cum;
        }
        __syncthreads();
        int cb = misc[2];
        for (int w = tid; w < WPM; w += T) {
            unsigned bits = sO[w];
            int r = w / 6, jbase = (w - r*6) * 32;
            while (bits) {
                int bpos = __ffs(bits) - 1;
                bits &= bits - 1;
                int key = gkeys[r*WW + jbase + bpos];
                if ((key >> 8) == cb) atomicAdd(&fine[key & 255], 1);
            }
        }
        __syncthreads();
        if (tid == 0) {
            int cum = 0, key95 = cb << 8;
            for (int k = 0; k < 256; k++) {
                cum += fine[k];
                if (cum >= misc[3]) { key95 += k; break; }
            }
            int keymax = misc[1];
            d_res[m*2+0] = (key95  == SENT_KEY) ? sqrtf(1e9f) : sqrtf((float)key95);
            d_res[m*2+1] = (keymax == SENT_KEY) ? sqrtf(1e9f) : sqrtf((float)keymax);
        }
    }

    // ---- G: final reduce by last mask to finish (order-independent -> deterministic)
    __threadfence();
    __syncthreads();
    if (tid == 0 && atomicAdd(&d_done, 1) == NM - 1) {
        __threadfence();
        float s100 = 0.0f, s95 = 0.0f;
        #pragma unroll
        for (int p = 0; p < NP; p++) {
            s95  += fmaxf(d_res[(2*p)*2 + 0], d_res[(2*p+1)*2 + 0]);
            s100 += fmaxf(d_res[(2*p)*2 + 1], d_res[(2*p+1)*2 + 1]);
        }
        out[0] = s100 / (float)NP;
        out[1] = s95  / (float)NP;
        d_done = 0;   // reset for next replay
    }
}

extern "C" void kernel_launch(void* const* d_in, const int* in_sizes, int n_in,
                              void* d_out, int out_size) {
    const float* logits = (const float*)d_in[0];
    const int*   target = (const int*)d_in[1];
    float* out = (float*)d_out;

    cudaFuncSetAttribute(mega_kernel, cudaFuncAttributeMaxDynamicSharedMemorySize, SMEM_TOTAL);
    argmax_kernel<<<(BB*HW + 255)/256, 256>>>(logits);
    mega_kernel<<<NM, 1024, SMEM_TOTAL>>>(target, out);
}

// round 17
// speedup vs baseline: 2.9966x; 1.2119x over previous
#include <cuda_runtime.h>
#include <math.h>

#define BB 8
#define CC 4
#define HH 192
#define WW 192
#define HW (HH*WW)
#define NP 24          // (batch, class) pairs
#define NM 48          // (pair, direction)
#define SENT_KEY 73727 // key for empty source surface (f = 1e9)
#define WPM 1152       // u32 words per mask bitmap (6 per row)
#define NSEG 8
#define SEGR 24
#define GEMPTY (1 << 27)
#define LIST_MAX 20480

// dynamic smem layout (bytes)
#define OFF_G     0        // int [HW] 147456 (C1 scratch: dn u16 | up u16; final: d^2 or GEMPTY)
#define OFF_LIST  147456   // u16 [LIST_MAX] 40960
#define OFF_FGP   188416   // u32 [1152]
#define OFF_FGG   193024   // u32 [1152]
#define OFF_SFP   197632   // u32 [1152]
#define OFF_SFG   202240   // u32 [1152]
#define OFF_OUTD  206848   // u8 [NSEG*192]
#define OFF_OUTU  208384   // u8 [NSEG*192]
#define OFF_INCD  209920   // u8 [NSEG*192]
#define OFF_INCU  211456   // u8 [NSEG*192]
#define OFF_ROWC  212992   // int [192]
#define OFF_ROWO  213760   // int [192]
#define OFF_HIST  214528   // int [288]
#define OFF_FINE  215680   // int [256]
#define OFF_MISC  216704   // int [8]
#define SMEM_TOTAL 216736

__device__ __align__(16) unsigned char d_pred[BB*HW];
__device__ int   d_keys[NM*HW];   // per-mask keys at list offsets
__device__ float d_res[NM*2];     // [m][0]=p95, [m][1]=p100
__device__ int   d_done;

extern __shared__ char smem[];

// ---------------------------------------------------------------- K1: argmax (softmax monotone; first-max ties)
__global__ void argmax_kernel(const float* __restrict__ logits) {
    int idx = blockIdx.x*blockDim.x + threadIdx.x;
    if (idx == 0) d_done = 0;
    if (idx >= BB*HW) return;
    int b = idx / HW;
    int p = idx - b*HW;
    const float* base = logits + (size_t)b*CC*HW + p;
    float v0 = base[0];
    float v1 = base[HW];
    float v2 = base[2*HW];
    float v3 = base[3*HW];
    float bv = v0; int bi = 0;
    if (v1 > bv) { bv = v1; bi = 1; }
    if (v2 > bv) { bv = v2; bi = 2; }
    if (v3 > bv) { bv = v3; bi = 3; }
    d_pred[idx] = (unsigned char)bi;
}

// ---------------------------------------------------------------- K2: one mask per block, fully fused
__global__ void __launch_bounds__(1024) mega_kernel(const int* __restrict__ target,
                                                    float* __restrict__ out) {
    int*            gS   = (int*)(smem + OFF_G);
    unsigned short* list = (unsigned short*)(smem + OFF_LIST);
    unsigned* fgP = (unsigned*)(smem + OFF_FGP);
    unsigned* fgG = (unsigned*)(smem + OFF_FGG);
    unsigned* sfP = (unsigned*)(smem + OFF_SFP);
    unsigned* sfG = (unsigned*)(smem + OFF_SFG);
    unsigned char* outd = (unsigned char*)(smem + OFF_OUTD);
    unsigned char* outu = (unsigned char*)(smem + OFF_OUTU);
    unsigned char* incd = (unsigned char*)(smem + OFF_INCD);
    unsigned char* incu = (unsigned char*)(smem + OFF_INCU);
    int* rowc = (int*)(smem + OFF_ROWC);
    int* rowo = (int*)(smem + OFF_ROWO);
    int* hist = (int*)(smem + OFF_HIST);
    int* fine = (int*)(smem + OFF_FINE);
    int* misc = (int*)(smem + OFF_MISC);

    const int T = 1024;
    int m = blockIdx.x;
    int pairI = m >> 1;
    int b = pairI / 3;
    int c = pairI - b*3 + 1;
    int tid = threadIdx.x;
    int lane = tid & 31;
    int wid = tid >> 5;

    // ---- A: fg bitmaps from pred bytes / int32 target (word-per-thread, no atomics)
    // target is int32 (JAX x64-disabled downcasts the reference's int64)
    {
        unsigned crep = (unsigned)c * 0x01010101u;
        const uint4* pb = (const uint4*)(d_pred + b*HW);
        const int4*  tb = (const int4*)(target + (size_t)b*HW);
        for (int k = tid; k < WPM; k += T) {
            unsigned wp = 0;
            uint4 pa = pb[k*2], pc = pb[k*2 + 1];
            #define NIB(word, sh) { \
                unsigned nb = ((__vcmpeq4(word, crep) & 0x01010101u) * 0x01020408u) >> 24; \
                wp |= nb << (sh); }
            NIB(pa.x, 0) NIB(pa.y, 4) NIB(pa.z, 8) NIB(pa.w, 12)
            NIB(pc.x, 16) NIB(pc.y, 20) NIB(pc.z, 24) NIB(pc.w, 28)
            #undef NIB
            fgP[k] = wp;
            unsigned wg = 0;
            #pragma unroll
            for (int q = 0; q < 8; q++) {
                int4 tv = tb[k*8 + q];
                wg |= ((tv.x==c)?1u:0u) << (4*q);
                wg |= ((tv.y==c)?2u:0u) << (4*q);
                wg |= ((tv.z==c)?4u:0u) << (4*q);
                wg |= ((tv.w==c)?8u:0u) << (4*q);
            }
            fgG[k] = wg;
        }
    }
    if (tid == 0) misc[1] = 0;
    for (int k = tid; k < 288; k += T) hist[k] = 0;
    if (tid < 256) fine[tid] = 0;
    __syncthreads();

    // ---- B: 4-neighbor surfaces via bit ops (image border = background)
    for (int idx = tid; idx < 2*WPM; idx += T) {
        const unsigned* fg = (idx < WPM) ? fgP : fgG;
        unsigned* sf = (idx < WPM) ? sfP : sfG;
        int k = (idx < WPM) ? idx : idx - WPM;
        int i = k / 6, w = k - (k/6)*6;
        unsigned f  = fg[k];
        unsigned up = (i > 0)    ? fg[k-6] : 0u;
        unsigned dn = (i < HH-1) ? fg[k+6] : 0u;
        unsigned lw = (w > 0) ? fg[k-1] : 0u;
        unsigned nx = (w < 5) ? fg[k+1] : 0u;
        unsigned lf = (f << 1) | (lw >> 31);
        unsigned rt = (f >> 1) | (nx << 31);
        sf[k] = f & ~(up & dn & lf & rt);
    }
    __syncthreads();

    const unsigned* sS = (m & 1) ? sfG : sfP;   // source surface (distance field of mask m)
    const unsigned* sO = (m & 1) ? sfP : sfG;   // opposite surface (sample points)

    // ---- C1: independent down/up segment scans (3072 tasks, 24-deep, all warps)
    // down writes low u16, up writes high u16 of the same g word (byte-granular, no race)
    for (int t = tid; t < 2*NSEG*WW; t += T) {
        int down = (t < NSEG*WW);
        int tt = down ? t : t - NSEG*WW;
        int s = tt / WW, j = tt - s*WW;
        int r0 = s*SEGR;
        int ws = j >> 5; unsigned bm = 1u << (j & 31);
        unsigned short* gh = (unsigned short*)gS;
        int cnt = 255;
        if (down) {
            #pragma unroll
            for (int k = 0; k < SEGR; k++) {
                bool sv = (sS[(r0 + k)*6 + ws] & bm) != 0;
                cnt = sv ? 0 : min(cnt + 1, 255);
                gh[((r0 + k)*WW + j)*2] = (unsigned short)cnt;
            }
            outd[s*WW + j] = (unsigned char)cnt;
        } else {
            #pragma unroll
            for (int k = SEGR - 1; k >= 0; k--) {
                bool sv = (sS[(r0 + k)*6 + ws] & bm) != 0;
                cnt = sv ? 0 : min(cnt + 1, 255);
                gh[((r0 + k)*WW + j)*2 + 1] = (unsigned short)cnt;
            }
            outu[s*WW + j] = (unsigned char)cnt;
        }
    }
    __syncthreads();

    // ---- C2 (threads 0-191): per-column incoming distances across segments
    //      D1 (threads 256-447, concurrent): per-row popcounts of the sample surface
    if (tid < WW) {
        int j = tid;
        int a = 255;
        incd[0*WW + j] = 255;
        #pragma unroll
        for (int s = 1; s < NSEG; s++) {
            a = min(255, min((int)outd[(s-1)*WW + j], a + SEGR));
            incd[s*WW + j] = (unsigned char)a;
        }
        a = 255;
        incu[(NSEG-1)*WW + j] = 255;
        #pragma unroll
        for (int s = NSEG - 2; s >= 0; s--) {
            a = min(255, min((int)outu[(s+1)*WW + j], a + SEGR));
            incu[s*WW + j] = (unsigned char)a;
        }
    } else if (tid >= 256 && tid < 256 + HH) {
        int r = tid - 256;
        int s = 0;
        #pragma unroll
        for (int w = 0; w < 6; w++) s += __popc(sO[r*6 + w]);
        rowc[r] = s;
    }
    __syncthreads();

    // ---- C3: combine -> g int d^2 (GEMPTY = no surface in column)
    for (int pos = tid; pos < HW; pos += T) {
        int i = pos / WW, j = pos - (pos/WW)*WW;
        int s = i / SEGR, il = i - s*SEGR;
        unsigned pv = (unsigned)gS[pos];
        int dglob = min((int)(pv & 0xFFFF), min(255, (int)incd[s*WW + j] + il + 1));
        int uglob = min((int)(pv >> 16),   min(255, (int)incu[s*WW + j] + (SEGR - il)));
        int d = min(dglob, uglob);
        gS[pos] = (d >= HH) ? GEMPTY : d*d;
    }
    // ---- D2 (warp 0 after its C3 share): exclusive prefix over 192 row counts
    __syncthreads();
    if (tid < 32) {
        int loc[6]; int lsum = 0;
        #pragma unroll
        for (int k = 0; k < 6; k++) { loc[k] = lsum; lsum += rowc[tid*6 + k]; }
        int x = lsum;
        #pragma unroll
        for (int off = 1; off < 32; off <<= 1) {
            int y = __shfl_up_sync(0xffffffffu, x, off);
            if (lane >= off) x += y;
        }
        int excl = x - lsum;
        #pragma unroll
        for (int k = 0; k < 6; k++) rowo[tid*6 + k] = excl + loc[k];
        if (tid == 31) misc[0] = x;   // total sample count n
    }
    __syncthreads();
    int n = misc[0];

    // ---- D3: scatter (row,col) samples at prefix offsets (no atomics)
    for (int r = wid; r < HH; r += 32) {
        int base = rowo[r];
        #pragma unroll
        for (int w = 0; w < 6; w++) {
            unsigned bits = sO[r*6 + w];
            if ((bits >> lane) & 1)
                list[base + __popc(bits & ((1u << lane) - 1u))] =
                    (unsigned short)((r << 8) | (w*32 + lane));
            base += __popc(bits);
        }
    }
    __syncthreads();

    if (n == 0) {
        if (tid == 0) { d_res[m*2] = INFINITY; d_res[m*2+1] = INFINITY; }
    } else {
        // ---- E: pure-int pruned min-plus, one sample per thread (balanced batches)
        // f = min_jp (j-jp)^2 + g[jp]; outward scan stops when dd^2 >= v (g >= 0 -> exact).
        // Real candidates are ints <= 72962 < GEMPTY, so int min == reference f32 min.
        int* gkeys = d_keys + m*HW;
        int locmax = 0;
        for (int s0 = 0; s0 < n; s0 += T) {
            int s = s0 + tid;
            bool act = (s < n);
            int key = 0;
            if (act) {
                int e = (int)list[s];
                int r = e >> 8, jj = e & 255;
                const int* grow = gS + r*WW;
                int v = grow[jj];
                for (int dd = 1; dd < WW; dd += 2) {
                    int d2a = dd*dd;
                    if (d2a >= v) break;
                    int d2b = (dd+1)*(dd+1);
                    int jl = jj - dd, jr = jj + dd;
                    int ca = (jl >= 0)     ? d2a + grow[jl]   : (1 << 29);
                    int cb = (jr < WW)     ? d2a + grow[jr]   : (1 << 29);
                    int cc = (jl - 1 >= 0) ? d2b + grow[jl-1] : (1 << 29);
                    int cd = (jr + 1 < WW) ? d2b + grow[jr+1] : (1 << 29);
                    v = min(min(v, min(ca, cb)), min(cc, cd));
                }
                key = (v > 73000) ? SENT_KEY : v;      // exact integer or empty-path
                gkeys[s] = key;
                locmax = max(locmax, key);
            }
            unsigned am = __ballot_sync(0xffffffffu, act);
            if (act) {
                int bin = key >> 8;
                unsigned grp = __match_any_sync(am, bin);
                if ((int)(__ffs(grp) - 1) == lane) atomicAdd(&hist[bin], __popc(grp));
            }
        }
        #pragma unroll
        for (int off = 16; off > 0; off >>= 1) locmax = max(locmax, __shfl_down_sync(0xffffffffu, locmax, off));
        if (lane == 0 && locmax > 0) atomicMax(&misc[1], locmax);
        __syncthreads();

        // ---- F: p95 = rank ceil(0.95f*n) via coarse+fine; p100 = max
        if (tid == 0) {
            int r95 = (int)ceilf(0.95f * (float)n);    // matches jnp f32 semantics
            r95 = max(1, min(r95, n));
            int cum = 0, cb = 287;
            for (int k = 0; k < 288; k++) {
                if (cum + hist[k] >= r95) { cb = k; break; }
                cum += hist[k];
            }
            misc[2] = cb; misc[3] = r95 - cum;
        }
        __syncthreads();
        int cbv = misc[2];
        for (int s = tid; s < n; s += T) {
            int key = gkeys[s];
            bool hit = ((key >> 8) == cbv);
            unsigned am = __activemask();
            unsigned hm = __ballot_sync(am, hit);
            if (hit) {
                int fb = key & 255;
                unsigned grp = __match_any_sync(hm, fb);
                if ((int)(__ffs(grp) - 1) == lane) atomicAdd(&fine[fb], __popc(grp));
            }
        }
        __syncthreads();
        if (tid == 0) {
            int cum = 0, key95 = cbv << 8;
            for (int k = 0; k < 256; k++) {
                cum += fine[k];
                if (cum >= misc[3]) { key95 += k; break; }
            }
            int keymax = misc[1];
            d_res[m*2+0] = (key95  == SENT_KEY) ? sqrtf(1e9f) : sqrtf((float)key95);
            d_res[m*2+1] = (keymax == SENT_KEY) ? sqrtf(1e9f) : sqrtf((float)keymax);
        }
    }

    // ---- G: final reduce by last mask to finish (order-independent -> deterministic)
    __threadfence();
    __syncthreads();
    if (tid == 0 && atomicAdd(&d_done, 1) == NM - 1) {
        __threadfence();
        float s100 = 0.0f, s95 = 0.0f;
        #pragma unroll
        for (int p = 0; p < NP; p++) {
            s95  += fmaxf(d_res[(2*p)*2 + 0], d_res[(2*p+1)*2 + 0]);
            s100 += fmaxf(d_res[(2*p)*2 + 1], d_res[(2*p+1)*2 + 1]);
        }
        out[0] = s100 / (float)NP;
        out[1] = s95  / (float)NP;
        d_done = 0;   // reset for next replay
    }
}

extern "C" void kernel_launch(void* const* d_in, const int* in_sizes, int n_in,
                              void* d_out, int out_size) {
    const float* logits = (const float*)d_in[0];
    const int*   target = (const int*)d_in[1];
    float* out = (float*)d_out;

    cudaFuncSetAttribute(mega_kernel, cudaFuncAttributeMaxDynamicSharedMemorySize, SMEM_TOTAL);
    argmax_kernel<<<(BB*HW + 255)/256, 256>>>(logits);
    mega_kernel<<<NM, 1024, SMEM_TOTAL>>>(target, out);
}